// round 5
// baseline (speedup 1.0000x reference)
#include <cuda_runtime.h>
#include <cuda_bf16.h>
#include <cuda_fp8.h>
#include <math.h>
#include <stdint.h>

// NT-Xent loss. B=4096, D=512. Fused FP8(e4m3) QMMA sim-GEMM with exp+row-sum
// epilogue. 148 persistent CTAs, static contiguous work partition.
// z normalized, scaled by 16, quantized to e4m3 -> accumulator = 256 * sim.

#define D 512
#define MAXN 8192
#define EPI_SCALE (2.0f / 256.0f)   // (1/T) / 16^2
#define NCTA 148
#define NCHUNK 16          // 512-col chunks per rowTile
#define NITEMS (64 * NCHUNK)

#define TM 128
#define TNC 128
#define KCHUNK 128         // fp8 K elems per B stage

// SMEM layout (fp8: 1 byte/elem)
#define SA_OFF 0
#define SA_BYTES (TM * D)                 // 65536
#define SB_OFF SA_BYTES
#define SB_BYTES (TNC * KCHUNK)           // 16384 per stage
#define NSTAGE 3
#define SRED_OFF (SB_OFF + NSTAGE * SB_BYTES)
#define SMEM_TOTAL (SRED_OFF + 128 * 2 * 4)

__device__ uint8_t g_znb[(size_t)MAXN * D];   // e4m3 of 16*zn
__device__ float g_rinv[MAXN];
__device__ float g_part[NCHUNK * MAXN];
__device__ float g_loss[MAXN];

__device__ __forceinline__ uint32_t smem_u32(const void* p) {
    uint32_t a;
    asm("{ .reg .u64 t; cvta.to.shared.u64 t, %1; cvt.u32.u64 %0, t; }" : "=r"(a) : "l"(p));
    return a;
}
__device__ __forceinline__ void ldsm4(uint32_t* r, uint32_t addr) {
    asm volatile("ldmatrix.sync.aligned.m8n8.x4.shared.b16 {%0,%1,%2,%3}, [%4];"
                 : "=r"(r[0]), "=r"(r[1]), "=r"(r[2]), "=r"(r[3]) : "r"(addr));
}
__device__ __forceinline__ void mma_fp8(float* c, const uint32_t* a, const uint32_t* b) {
    asm volatile(
        "mma.sync.aligned.m16n8k32.row.col.f32.e4m3.e4m3.f32 "
        "{%0,%1,%2,%3}, {%4,%5,%6,%7}, {%8,%9}, {%0,%1,%2,%3};"
        : "+f"(c[0]), "+f"(c[1]), "+f"(c[2]), "+f"(c[3])
        : "r"(a[0]), "r"(a[1]), "r"(a[2]), "r"(a[3]), "r"(b[0]), "r"(b[1]));
}

// ---------------------------------------------------------------------------
// 1) normalize -> e4m3(16*zn), inverse norms; zero g_part
// ---------------------------------------------------------------------------
__global__ void normalize_kernel(const float* __restrict__ zi,
                                 const float* __restrict__ zj, int B) {
    int row = blockIdx.x;
    const float* src = (row < B) ? (zi + (size_t)row * D) : (zj + (size_t)(row - B) * D);
    int t = threadIdx.x;
    float4 v = *(const float4*)(src + t * 4);
    float ss = v.x * v.x + v.y * v.y + v.z * v.z + v.w * v.w;
    __shared__ float red[128];
    red[t] = ss;
    __syncthreads();
#pragma unroll
    for (int s = 64; s > 0; s >>= 1) {
        if (t < s) red[t] += red[t + s];
        __syncthreads();
    }
    float rinv = rsqrtf(red[0]);
    float sc = rinv * 16.0f;
    uchar4 q;
    q.x = (uint8_t)__nv_cvt_float_to_fp8(v.x * sc, __NV_SATFINITE, __NV_E4M3);
    q.y = (uint8_t)__nv_cvt_float_to_fp8(v.y * sc, __NV_SATFINITE, __NV_E4M3);
    q.z = (uint8_t)__nv_cvt_float_to_fp8(v.z * sc, __NV_SATFINITE, __NV_E4M3);
    q.w = (uint8_t)__nv_cvt_float_to_fp8(v.w * sc, __NV_SATFINITE, __NV_E4M3);
    *(uchar4*)(g_znb + (size_t)row * D + t * 4) = q;
    if (t == 0) g_rinv[row] = rinv;
    if (t < NCHUNK) g_part[t * MAXN + row] = 0.0f;
}

// ---------------------------------------------------------------------------
// 2) fused FP8 QMMA GEMM + exp row-sum
// ---------------------------------------------------------------------------
__device__ __forceinline__ void prefetchB(const uint8_t* __restrict__ znb,
                                          int colBase, int kc, uint32_t smemBuf, int tid) {
#pragma unroll
    for (int i = 0; i < 4; i++) {
        int idx = tid + i * 256;
        int n = idx >> 3;
        int c = idx & 7;
        const void* g = znb + (size_t)(colBase + n) * D + kc * KCHUNK + c * 16;
        uint32_t s = smemBuf + n * 128 + ((c ^ (n & 7)) << 4);
        asm volatile("cp.async.cg.shared.global [%0], [%1], 16;" :: "r"(s), "l"(g));
    }
    asm volatile("cp.async.commit_group;");
}

__global__ void __launch_bounds__(256, 1) denom_kernel() {
    extern __shared__ char smem[];
    const int tid = threadIdx.x;
    const int lane = tid & 31;
    const int wid = tid >> 5;
    const int warpM = wid & 3;
    const int warpN = wid >> 2;
    const int cta = blockIdx.x;

    const uint8_t* __restrict__ znb = g_znb;
    uint32_t sA = smem_u32(smem) + SA_OFF;
    uint32_t sB = smem_u32(smem) + SB_OFF;
    float (*red)[2] = (float(*)[2])(smem + SRED_OFF);

    const int aRow = warpM * 32 + (lane & 15);
    const uint32_t aBase = sA + aRow * 512;       // A row = 512 B
    const int aXor = aRow & 7;
    const int aC = lane >> 4;
    const int bRow = warpN * 64 + (lane & 7) + ((lane >> 4) << 3);
    const int bXor = bRow & 7;
    const int bC = (lane >> 3) & 1;

    int istart = (cta * NITEMS) / NCTA;
    const int iend = ((cta + 1) * NITEMS) / NCTA;

    while (istart < iend) {
        const int rowTile = istart >> 4;
        const int segEnd = min(iend, (rowTile + 1) << 4);
        const int chunk0 = istart & 15;
        const int nTiles = (segEnd - istart) * 4;
        const int rowBase = rowTile * TM;
        const int segCol = chunk0 * 512;

        // ---- A tile [128 x 512 fp8], XOR-swizzled, via cp.async ----
        asm volatile("cp.async.wait_group 0;");
        __syncthreads();
#pragma unroll 4
        for (int idx = tid; idx < TM * 32; idx += 256) {
            int r = idx >> 5;
            int c = idx & 31;
            const void* g = znb + (size_t)(rowBase + r) * D + c * 16;
            uint32_t s = sA + r * 512 + ((c ^ (r & 7)) << 4);
            asm volatile("cp.async.cg.shared.global [%0], [%1], 16;" :: "r"(s), "l"(g));
        }
        asm volatile("cp.async.commit_group;");
        asm volatile("cp.async.wait_group 0;");
        __syncthreads();

        float acc[2][8][4];
#pragma unroll
        for (int mt = 0; mt < 2; mt++)
#pragma unroll
            for (int nt = 0; nt < 8; nt++)
#pragma unroll
                for (int j = 0; j < 4; j++) acc[mt][nt][j] = 0.f;
        float part[2][2] = {{0.f, 0.f}, {0.f, 0.f}};

        const int nIts = nTiles * 4;   // 4 k-chunks per 128-col tile
        prefetchB(znb, segCol, 0, sB, tid);
        if (nIts > 1) prefetchB(znb, segCol, 1, sB + SB_BYTES, tid);
        else asm volatile("cp.async.commit_group;");

        int buf = 0, pbuf = 2;
        for (int it = 0; it < nIts; ++it) {
            const int tile = it >> 2;
            const int kc = it & 3;
            asm volatile("cp.async.wait_group 1;");
            __syncthreads();

            int itn = it + 2;
            if (itn < nIts)
                prefetchB(znb, segCol + (itn >> 2) * TNC, itn & 3, sB + pbuf * SB_BYTES, tid);
            else
                asm volatile("cp.async.commit_group;");
            pbuf = (pbuf == 2) ? 0 : pbuf + 1;

            const uint32_t bufB = sB + buf * SB_BYTES;
            buf = (buf == 2) ? 0 : buf + 1;
#pragma unroll
            for (int s = 0; s < 4; ++s) {       // 4 x k32 per 128-fp8 chunk
                uint32_t af[2][4];
#pragma unroll
                for (int mt = 0; mt < 2; mt++)
                    ldsm4(af[mt], aBase + mt * 8192 +
                                  (((kc * 8 + s * 2 + aC) ^ aXor) << 4));
#pragma unroll
                for (int bg = 0; bg < 4; bg++) {
                    uint32_t bf[4];
                    ldsm4(bf, bufB + (bRow + bg * 16) * 128 +
                              (((s * 2 + bC) ^ bXor) << 4));
#pragma unroll
                    for (int mt = 0; mt < 2; mt++) {
                        mma_fp8(acc[mt][bg * 2], af[mt], bf);
                        mma_fp8(acc[mt][bg * 2 + 1], af[mt], bf + 2);
                    }
                }
            }

            if (kc == 3) {
                int colWBase = segCol + tile * TNC + warpN * 64 + (lane & 3) * 2;
#pragma unroll
                for (int mt = 0; mt < 2; mt++) {
                    int r0 = rowBase + warpM * 32 + mt * 16 + (lane >> 2);
                    int r1 = r0 + 8;
#pragma unroll
                    for (int nt = 0; nt < 8; nt++) {
                        int c0 = colWBase + nt * 8;
                        float e0 = __expf(acc[mt][nt][0] * EPI_SCALE);
                        float e1 = __expf(acc[mt][nt][1] * EPI_SCALE);
                        float e2 = __expf(acc[mt][nt][2] * EPI_SCALE);
                        float e3 = __expf(acc[mt][nt][3] * EPI_SCALE);
                        part[mt][0] += (c0 != r0 ? e0 : 0.f) + (c0 + 1 != r0 ? e1 : 0.f);
                        part[mt][1] += (c0 != r1 ? e2 : 0.f) + (c0 + 1 != r1 ? e3 : 0.f);
                        acc[mt][nt][0] = 0.f; acc[mt][nt][1] = 0.f;
                        acc[mt][nt][2] = 0.f; acc[mt][nt][3] = 0.f;
                    }
                }
            }
        }

        __syncthreads();
#pragma unroll
        for (int mt = 0; mt < 2; mt++)
#pragma unroll
            for (int h = 0; h < 2; h++) {
                float p = part[mt][h];
                p += __shfl_xor_sync(0xffffffffu, p, 1);
                p += __shfl_xor_sync(0xffffffffu, p, 2);
                part[mt][h] = p;
            }
        if ((lane & 3) == 0) {
#pragma unroll
            for (int mt = 0; mt < 2; mt++)
#pragma unroll
                for (int h = 0; h < 2; h++) {
                    int rl = warpM * 32 + mt * 16 + (lane >> 2) + 8 * h;
                    red[rl][warpN] = part[mt][h];
                }
        }
        __syncthreads();
        if (tid < TM)
            g_part[chunk0 * MAXN + rowBase + tid] = red[tid][0] + red[tid][1];

        istart = segEnd;
    }
}

// ---------------------------------------------------------------------------
// 3) positives (fp32, from raw inputs) + per-row loss
// ---------------------------------------------------------------------------
__global__ void loss_kernel(const float* __restrict__ zi,
                            const float* __restrict__ zj, int B) {
    int warp = (blockIdx.x * blockDim.x + threadIdx.x) >> 5;
    int lane = threadIdx.x & 31;
    int N = 2 * B;
    if (warp >= N) return;
    int row = (warp < B) ? warp : (warp - B);
    const float* a = zi + (size_t)row * D;
    const float* b = zj + (size_t)row * D;
    float dot = 0.f;
#pragma unroll
    for (int q = 0; q < D / (32 * 4); q++) {
        float4 va = *(const float4*)(a + (q * 32 + lane) * 4);
        float4 vb = *(const float4*)(b + (q * 32 + lane) * 4);
        dot += va.x * vb.x + va.y * vb.y + va.z * vb.z + va.w * vb.w;
    }
#pragma unroll
    for (int o = 16; o > 0; o >>= 1) dot += __shfl_xor_sync(0xffffffffu, dot, o);
    if (lane == 0) {
        int prow = (warp < B) ? (warp + B) : (warp - B);
        float sim = dot * g_rinv[warp] * g_rinv[prow] * 2.0f;
        float denom = 0.f;
#pragma unroll
        for (int s = 0; s < NCHUNK; s++) denom += g_part[s * MAXN + warp];
        g_loss[warp] = logf(denom + 1e-8f) - sim;
    }
}

// ---------------------------------------------------------------------------
// 4) deterministic mean
// ---------------------------------------------------------------------------
__global__ void mean_kernel(float* __restrict__ out, int N) {
    __shared__ float red[256];
    int t = threadIdx.x;
    float s = 0.f;
    for (int i = t; i < N; i += 256) s += g_loss[i];
    red[t] = s;
    __syncthreads();
#pragma unroll
    for (int st = 128; st > 0; st >>= 1) {
        if (t < st) red[t] += red[t + st];
        __syncthreads();
    }
    if (t == 0) out[0] = red[0] / (float)N;
}

// ---------------------------------------------------------------------------
extern "C" void kernel_launch(void* const* d_in, const int* in_sizes, int n_in,
                              void* d_out, int out_size) {
    const float* zi = (const float*)d_in[0];
    const float* zj = (const float*)d_in[1];
    int B = in_sizes[0] / D;  // 4096
    int N = 2 * B;            // 8192

    cudaFuncSetAttribute(denom_kernel, cudaFuncAttributeMaxDynamicSharedMemorySize, SMEM_TOTAL);

    normalize_kernel<<<N, 128>>>(zi, zj, B);
    denom_kernel<<<NCTA, 256, SMEM_TOTAL>>>();
    loss_kernel<<<(N * 32 + 255) / 256, 256>>>(zi, zj, B);
    mean_kernel<<<1, 256>>>((float*)d_out, N);
}

// round 6
// speedup vs baseline: 1.8168x; 1.8168x over previous
#include <cuda_runtime.h>
#include <cuda_bf16.h>
#include <math.h>
#include <stdint.h>

// NT-Xent loss. B=4096, D=512. Fused bf16 HMMA sim-GEMM exploiting symmetry:
// only upper-triangle 128x128 tiles computed; each off-diag tile emits both
// row-sums (band r) and col-sums (band c). 148 CTAs, static partition.

#define D 512
#define MAXN 8192
#define TEMP_INV 2.0f
#define NCTA 148
#define NB 64              // 128-row bands
#define NTILES 2080        // 32*33 + 32*32

#define TM 128
#define KCHUNK 128

// SMEM layout
#define SA_OFF 0
#define SA_BYTES (TM * D * 2)            // 131072
#define SB_OFF SA_BYTES
#define SB_BYTES (TM * KCHUNK * 2)       // 32768 per stage
#define NSTAGE 3
#define SRED_OFF (SB_OFF + NSTAGE * SB_BYTES)   // 229376
#define SMEM_TOTAL (SRED_OFF + 2048)            // 231424

__device__ __nv_bfloat16 g_znb[(size_t)MAXN * D];
__device__ float g_rinv[MAXN];
__device__ float g_rs[NB * 33 * 128];
__device__ float g_cs[NB * 33 * 128];
__device__ float g_loss[MAXN];

__device__ __forceinline__ uint32_t smem_u32(const void* p) {
    uint32_t a;
    asm("{ .reg .u64 t; cvta.to.shared.u64 t, %1; cvt.u32.u64 %0, t; }" : "=r"(a) : "l"(p));
    return a;
}
__device__ __forceinline__ void ldsm4(uint32_t* r, uint32_t addr) {
    asm volatile("ldmatrix.sync.aligned.m8n8.x4.shared.b16 {%0,%1,%2,%3}, [%4];"
                 : "=r"(r[0]), "=r"(r[1]), "=r"(r[2]), "=r"(r[3]) : "r"(addr));
}
__device__ __forceinline__ void mma_bf16(float* c, const uint32_t* a, const uint32_t* b) {
    asm volatile(
        "mma.sync.aligned.m16n8k16.row.col.f32.bf16.bf16.f32 "
        "{%0,%1,%2,%3}, {%4,%5,%6,%7}, {%8,%9}, {%0,%1,%2,%3};"
        : "+f"(c[0]), "+f"(c[1]), "+f"(c[2]), "+f"(c[3])
        : "r"(a[0]), "r"(a[1]), "r"(a[2]), "r"(a[3]), "r"(b[0]), "r"(b[1]));
}

// tile t -> (band r, offset off, col band c)
__device__ __forceinline__ void tmap(int t, int& r, int& off, int& c) {
    if (t < 32 * 33) { r = t / 33; off = t - r * 33; }
    else { int u = t - 32 * 33; r = 32 + u / 32; off = u - (u / 32) * 32; }
    c = (r + off) & 63;
}

// ---------------------------------------------------------------------------
// 1) normalize -> bf16 znb + inverse norms
// ---------------------------------------------------------------------------
__global__ void normalize_kernel(const float* __restrict__ zi,
                                 const float* __restrict__ zj, int B) {
    int row = blockIdx.x;
    const float* src = (row < B) ? (zi + (size_t)row * D) : (zj + (size_t)(row - B) * D);
    int t = threadIdx.x;
    float4 v = *(const float4*)(src + t * 4);
    float ss = v.x * v.x + v.y * v.y + v.z * v.z + v.w * v.w;
    __shared__ float red[128];
    red[t] = ss;
    __syncthreads();
#pragma unroll
    for (int s = 64; s > 0; s >>= 1) {
        if (t < s) red[t] += red[t + s];
        __syncthreads();
    }
    float rinv = rsqrtf(red[0]);
    __nv_bfloat16* ob = g_znb + (size_t)row * D + t * 4;
    ob[0] = __float2bfloat16(v.x * rinv);
    ob[1] = __float2bfloat16(v.y * rinv);
    ob[2] = __float2bfloat16(v.z * rinv);
    ob[3] = __float2bfloat16(v.w * rinv);
    if (t == 0) g_rinv[row] = rinv;
}

// ---------------------------------------------------------------------------
// 2) symmetric fused HMMA GEMM
// ---------------------------------------------------------------------------
__device__ __forceinline__ void prefetchB(const __nv_bfloat16* __restrict__ znb,
                                          int colBase, int kc, uint32_t smemBuf, int tid) {
#pragma unroll
    for (int i = 0; i < 8; i++) {
        int idx = tid + i * 256;
        int n = idx >> 4;
        int c = idx & 15;
        const void* g = znb + (size_t)(colBase + n) * D + kc * KCHUNK + c * 8;
        uint32_t s = smemBuf + n * 256 + ((c ^ (n & 7)) << 4);
        asm volatile("cp.async.cg.shared.global [%0], [%1], 16;" :: "r"(s), "l"(g));
    }
    asm volatile("cp.async.commit_group;");
}

__device__ __forceinline__ void loadA(const __nv_bfloat16* __restrict__ znb,
                                      int rowBase, uint32_t sA, int tid) {
#pragma unroll 8
    for (int idx = tid; idx < TM * 64; idx += 256) {
        int r = idx >> 6;
        int c = idx & 63;
        const void* g = znb + (size_t)(rowBase + r) * D + c * 8;
        uint32_t s = sA + r * 1024 + ((c ^ (r & 7)) << 4);
        asm volatile("cp.async.cg.shared.global [%0], [%1], 16;" :: "r"(s), "l"(g));
    }
    asm volatile("cp.async.commit_group;");
}

__global__ void __launch_bounds__(256, 1) denom_kernel() {
    extern __shared__ char smem[];
    const int tid = threadIdx.x;
    const int lane = tid & 31;
    const int wid = tid >> 5;
    const int warpM = wid & 3;
    const int warpN = wid >> 2;
    const int cta = blockIdx.x;

    const __nv_bfloat16* __restrict__ znb = g_znb;
    uint32_t sA = smem_u32(smem) + SA_OFF;
    uint32_t sB = smem_u32(smem) + SB_OFF;
    float* scratch = (float*)(smem + SRED_OFF);

    const int aRow = warpM * 32 + (lane & 15);
    const uint32_t aBase = sA + aRow * 1024;
    const int aXor = aRow & 7;
    const int aC = lane >> 4;
    const int bRow = warpN * 64 + (lane & 7) + ((lane >> 4) << 3);
    const int bXor = bRow & 7;
    const int bC = (lane >> 3) & 1;

    const int istart = (cta * NTILES) / NCTA;
    const int iend = ((cta + 1) * NTILES) / NCTA;
    const int nIts = (iend - istart) * 4;

    int rcur, offcur, ccur;
    tmap(istart, rcur, offcur, ccur);
    int rprev = rcur;

    // prime: A band + first two B chunks
    loadA(znb, rcur * TM, sA, tid);
    asm volatile("cp.async.wait_group 0;");
    __syncthreads();
    prefetchB(znb, ccur * TM, 0, sB, tid);
    prefetchB(znb, ccur * TM, 1, sB + SB_BYTES, tid);

    float acc[2][8][4];
#pragma unroll
    for (int mt = 0; mt < 2; mt++)
#pragma unroll
        for (int nt = 0; nt < 8; nt++)
#pragma unroll
            for (int j = 0; j < 4; j++) acc[mt][nt][j] = 0.f;

    for (int git = 0; git < nIts; ++git) {
        const int kc = git & 3;
        if (kc == 0 && git > 0) {
            tmap(istart + (git >> 2), rcur, offcur, ccur);
            if (rcur != rprev) {
                asm volatile("cp.async.wait_group 0;");
                __syncthreads();
                loadA(znb, rcur * TM, sA, tid);
                asm volatile("cp.async.wait_group 0;");
                __syncthreads();
                rprev = rcur;
            }
        }
        asm volatile("cp.async.wait_group 1;");
        __syncthreads();

        // prefetch git+2
        if (git + 2 < nIts) {
            int r2, o2, c2;
            tmap(istart + ((git + 2) >> 2), r2, o2, c2);
            prefetchB(znb, c2 * TM, (git + 2) & 3, sB + ((git + 2) % 3) * SB_BYTES, tid);
        } else {
            asm volatile("cp.async.commit_group;");
        }

        const uint32_t bufB = sB + (git % 3) * SB_BYTES;
#pragma unroll
        for (int s = 0; s < 8; ++s) {
            uint32_t af[2][4];
#pragma unroll
            for (int mt = 0; mt < 2; mt++)
                ldsm4(af[mt], aBase + mt * 16384 + (((kc * 16 + s * 2 + aC) ^ aXor) << 4));
#pragma unroll
            for (int bg = 0; bg < 4; bg++) {
                uint32_t bf[4];
                ldsm4(bf, bufB + (bRow + bg * 16) * 256 + (((s * 2 + bC) ^ bXor) << 4));
#pragma unroll
                for (int mt = 0; mt < 2; mt++) {
                    mma_bf16(acc[mt][bg * 2], af[mt], bf);
                    mma_bf16(acc[mt][bg * 2 + 1], af[mt], bf + 2);
                }
            }
        }

        if (kc == 3) {
            // ---- epilogue: exp; row partials always, col partials if off!=0
            float rowp[2][2] = {{0.f, 0.f}, {0.f, 0.f}};
            float colp[8][2];
#pragma unroll
            for (int nt = 0; nt < 8; nt++) { colp[nt][0] = 0.f; colp[nt][1] = 0.f; }

            const int colWBase = ccur * TM + warpN * 64 + (lane & 3) * 2;
            const int r0g = rcur * TM + warpM * 32 + (lane >> 2);
            if (offcur == 0) {
#pragma unroll
                for (int mt = 0; mt < 2; mt++) {
                    int r0 = r0g + mt * 16, r1 = r0 + 8;
#pragma unroll
                    for (int nt = 0; nt < 8; nt++) {
                        int c0 = colWBase + nt * 8;
                        float e0 = __expf(acc[mt][nt][0] * TEMP_INV);
                        float e1 = __expf(acc[mt][nt][1] * TEMP_INV);
                        float e2 = __expf(acc[mt][nt][2] * TEMP_INV);
                        float e3 = __expf(acc[mt][nt][3] * TEMP_INV);
                        rowp[mt][0] += (c0 != r0 ? e0 : 0.f) + (c0 + 1 != r0 ? e1 : 0.f);
                        rowp[mt][1] += (c0 != r1 ? e2 : 0.f) + (c0 + 1 != r1 ? e3 : 0.f);
                        acc[mt][nt][0] = 0.f; acc[mt][nt][1] = 0.f;
                        acc[mt][nt][2] = 0.f; acc[mt][nt][3] = 0.f;
                    }
                }
            } else {
#pragma unroll
                for (int mt = 0; mt < 2; mt++) {
#pragma unroll
                    for (int nt = 0; nt < 8; nt++) {
                        float e0 = __expf(acc[mt][nt][0] * TEMP_INV);
                        float e1 = __expf(acc[mt][nt][1] * TEMP_INV);
                        float e2 = __expf(acc[mt][nt][2] * TEMP_INV);
                        float e3 = __expf(acc[mt][nt][3] * TEMP_INV);
                        rowp[mt][0] += e0 + e1;
                        rowp[mt][1] += e2 + e3;
                        colp[nt][0] += e0 + e2;
                        colp[nt][1] += e1 + e3;
                        acc[mt][nt][0] = 0.f; acc[mt][nt][1] = 0.f;
                        acc[mt][nt][2] = 0.f; acc[mt][nt][3] = 0.f;
                    }
                }
            }

            // row partials: reduce across lane&3 (cols within thread group)
#pragma unroll
            for (int mt = 0; mt < 2; mt++)
#pragma unroll
                for (int h = 0; h < 2; h++) {
                    float p = rowp[mt][h];
                    p += __shfl_xor_sync(0xffffffffu, p, 1);
                    p += __shfl_xor_sync(0xffffffffu, p, 2);
                    rowp[mt][h] = p;
                }
            if ((lane & 3) == 0) {
#pragma unroll
                for (int mt = 0; mt < 2; mt++)
#pragma unroll
                    for (int h = 0; h < 2; h++) {
                        int rl = warpM * 32 + mt * 16 + (lane >> 2) + 8 * h;
                        scratch[rl * 2 + warpN] = rowp[mt][h];
                    }
            }
            __syncthreads();
            if (tid < TM)
                g_rs[(rcur * 33 + offcur) * 128 + tid] = scratch[tid * 2] + scratch[tid * 2 + 1];

            if (offcur != 0) {
                // col partials: reduce across rows (lane>>2) via xor 4,8,16
                __syncthreads();
#pragma unroll
                for (int nt = 0; nt < 8; nt++)
#pragma unroll
                    for (int q = 0; q < 2; q++) {
                        float p = colp[nt][q];
                        p += __shfl_xor_sync(0xffffffffu, p, 4);
                        p += __shfl_xor_sync(0xffffffffu, p, 8);
                        p += __shfl_xor_sync(0xffffffffu, p, 16);
                        colp[nt][q] = p;
                    }
                if (lane < 4) {
#pragma unroll
                    for (int nt = 0; nt < 8; nt++)
#pragma unroll
                        for (int q = 0; q < 2; q++) {
                            int col = nt * 8 + lane * 2 + q;
                            scratch[(warpN * 4 + warpM) * 64 + col] = colp[nt][q];
                        }
                }
                __syncthreads();
                if (tid < TM) {
                    int wn = tid >> 6, cl = tid & 63;
                    float s = scratch[(wn * 4 + 0) * 64 + cl] + scratch[(wn * 4 + 1) * 64 + cl]
                            + scratch[(wn * 4 + 2) * 64 + cl] + scratch[(wn * 4 + 3) * 64 + cl];
                    g_cs[(rcur * 33 + offcur) * 128 + tid] = s;
                }
            }
        }
    }
}

// ---------------------------------------------------------------------------
// 3) gather denom slots + positives (fp32) -> per-row loss
// ---------------------------------------------------------------------------
__global__ void loss_kernel(const float* __restrict__ zi,
                            const float* __restrict__ zj, int B) {
    int warp = (blockIdx.x * blockDim.x + threadIdx.x) >> 5;
    int lane = threadIdx.x & 31;
    int N = 2 * B;
    if (warp >= N) return;

    // denominator gather
    int b = warp >> 7, lr = warp & 127;
    float d = g_rs[(b * 33 + lane) * 128 + lr];                 // rs off = 0..31
    if (lane == 0 && b < 32) d += g_rs[(b * 33 + 32) * 128 + lr];  // rs off = 32
    {
        int off2 = lane + 1;                                     // cs off = 1..32
        int rr = (b - off2 + 64) & 63;
        if (off2 < 32 || rr < 32) d += g_cs[(rr * 33 + off2) * 128 + lr];
    }
#pragma unroll
    for (int o = 16; o > 0; o >>= 1) d += __shfl_xor_sync(0xffffffffu, d, o);

    // positives from raw fp32 inputs
    int row = (warp < B) ? warp : (warp - B);
    const float* a = zi + (size_t)row * D;
    const float* bb = zj + (size_t)row * D;
    float dot = 0.f;
#pragma unroll
    for (int q = 0; q < D / (32 * 4); q++) {
        float4 va = *(const float4*)(a + (q * 32 + lane) * 4);
        float4 vb = *(const float4*)(bb + (q * 32 + lane) * 4);
        dot += va.x * vb.x + va.y * vb.y + va.z * vb.z + va.w * vb.w;
    }
#pragma unroll
    for (int o = 16; o > 0; o >>= 1) dot += __shfl_xor_sync(0xffffffffu, dot, o);

    if (lane == 0) {
        int prow = (warp < B) ? (warp + B) : (warp - B);
        float sim = dot * g_rinv[warp] * g_rinv[prow] * TEMP_INV;
        g_loss[warp] = logf(d + 1e-8f) - sim;
    }
}

// ---------------------------------------------------------------------------
// 4) deterministic mean
// ---------------------------------------------------------------------------
__global__ void mean_kernel(float* __restrict__ out, int N) {
    __shared__ float red[256];
    int t = threadIdx.x;
    float s = 0.f;
    for (int i = t; i < N; i += 256) s += g_loss[i];
    red[t] = s;
    __syncthreads();
#pragma unroll
    for (int st = 128; st > 0; st >>= 1) {
        if (t < st) red[t] += red[t + st];
        __syncthreads();
    }
    if (t == 0) out[0] = red[0] / (float)N;
}

// ---------------------------------------------------------------------------
extern "C" void kernel_launch(void* const* d_in, const int* in_sizes, int n_in,
                              void* d_out, int out_size) {
    const float* zi = (const float*)d_in[0];
    const float* zj = (const float*)d_in[1];
    int B = in_sizes[0] / D;  // 4096
    int N = 2 * B;            // 8192

    cudaFuncSetAttribute(denom_kernel, cudaFuncAttributeMaxDynamicSharedMemorySize, SMEM_TOTAL);

    normalize_kernel<<<N, 128>>>(zi, zj, B);
    denom_kernel<<<NCTA, 256, SMEM_TOTAL>>>();
    loss_kernel<<<(N * 32 + 255) / 256, 256>>>(zi, zj, B);
    mean_kernel<<<1, 256>>>((float*)d_out, N);
}

// round 7
// speedup vs baseline: 1.8698x; 1.0291x over previous
#include <cuda_runtime.h>
#include <cuda_bf16.h>
#include <math.h>
#include <stdint.h>

// NT-Xent loss. B=4096, D=512. Symmetric fused bf16 HMMA sim-GEMM.
// Inputs pre-scaled by sqrt(2*log2(e)) so epilogue is a bare ex2.
// Row partials accumulated in registers per band segment.

#define D 512
#define MAXN 8192
#define TEMP_INV 2.0f
#define QSCALE 1.6986436f   // sqrt(2 * log2(e)); acc = 2*log2(e)*sim
#define NCTA 148
#define NB 64
#define NTILES 2080

#define TM 128
#define KCHUNK 128

#define SA_OFF 0
#define SA_BYTES (TM * D * 2)
#define SB_OFF SA_BYTES
#define SB_BYTES (TM * KCHUNK * 2)
#define NSTAGE 3
#define SRED_OFF (SB_OFF + NSTAGE * SB_BYTES)
#define SMEM_TOTAL (SRED_OFF + 2048)

#define NLBLK 1024   // loss blocks (8 rows each)

__device__ __nv_bfloat16 g_znb[(size_t)MAXN * D];
__device__ float g_rinv[MAXN];
__device__ float g_rs[NB * 33 * 128];
__device__ float g_cs[NB * 33 * 128];
__device__ float g_bpart[NLBLK];
__device__ unsigned int g_ctr = 0;

__device__ __forceinline__ uint32_t smem_u32(const void* p) {
    uint32_t a;
    asm("{ .reg .u64 t; cvta.to.shared.u64 t, %1; cvt.u32.u64 %0, t; }" : "=r"(a) : "l"(p));
    return a;
}
__device__ __forceinline__ float ex2f(float x) {
    float r;
    asm("ex2.approx.f32 %0, %1;" : "=f"(r) : "f"(x));
    return r;
}
__device__ __forceinline__ void ldsm4(uint32_t* r, uint32_t addr) {
    asm volatile("ldmatrix.sync.aligned.m8n8.x4.shared.b16 {%0,%1,%2,%3}, [%4];"
                 : "=r"(r[0]), "=r"(r[1]), "=r"(r[2]), "=r"(r[3]) : "r"(addr));
}
__device__ __forceinline__ void mma_bf16(float* c, const uint32_t* a, const uint32_t* b) {
    asm volatile(
        "mma.sync.aligned.m16n8k16.row.col.f32.bf16.bf16.f32 "
        "{%0,%1,%2,%3}, {%4,%5,%6,%7}, {%8,%9}, {%0,%1,%2,%3};"
        : "+f"(c[0]), "+f"(c[1]), "+f"(c[2]), "+f"(c[3])
        : "r"(a[0]), "r"(a[1]), "r"(a[2]), "r"(a[3]), "r"(b[0]), "r"(b[1]));
}
__device__ __forceinline__ void tmap(int t, int& r, int& off, int& c) {
    if (t < 32 * 33) { r = t / 33; off = t - r * 33; }
    else { int u = t - 32 * 33; r = 32 + u / 32; off = u - (u / 32) * 32; }
    c = (r + off) & 63;
}

// ---------------------------------------------------------------------------
// 1) normalize -> bf16(zn * QSCALE) + inverse norms; zero g_rs
// ---------------------------------------------------------------------------
__global__ void normalize_kernel(const float* __restrict__ zi,
                                 const float* __restrict__ zj, int B) {
    int row = blockIdx.x;
    const float* src = (row < B) ? (zi + (size_t)row * D) : (zj + (size_t)(row - B) * D);
    int t = threadIdx.x;
    float4 v = *(const float4*)(src + t * 4);
    float ss = v.x * v.x + v.y * v.y + v.z * v.z + v.w * v.w;
    __shared__ float red[128];
    red[t] = ss;
    __syncthreads();
#pragma unroll
    for (int s = 64; s > 0; s >>= 1) {
        if (t < s) red[t] += red[t + s];
        __syncthreads();
    }
    float rinv = rsqrtf(red[0]);
    float sc = rinv * QSCALE;
    __nv_bfloat16* ob = g_znb + (size_t)row * D + t * 4;
    ob[0] = __float2bfloat16(v.x * sc);
    ob[1] = __float2bfloat16(v.y * sc);
    ob[2] = __float2bfloat16(v.z * sc);
    ob[3] = __float2bfloat16(v.w * sc);
    if (t == 0) g_rinv[row] = rinv;
    if (t < 33) g_rs[row * 33 + t] = 0.0f;   // covers all NB*33*128 slots
}

// ---------------------------------------------------------------------------
// 2) symmetric fused HMMA GEMM, segment-accumulated row sums
// ---------------------------------------------------------------------------
__device__ __forceinline__ void prefetchB(const __nv_bfloat16* __restrict__ znb,
                                          int colBase, int kc, uint32_t smemBuf, int tid) {
#pragma unroll
    for (int i = 0; i < 8; i++) {
        int idx = tid + i * 256;
        int n = idx >> 4;
        int c = idx & 15;
        const void* g = znb + (size_t)(colBase + n) * D + kc * KCHUNK + c * 8;
        uint32_t s = smemBuf + n * 256 + ((c ^ (n & 7)) << 4);
        asm volatile("cp.async.cg.shared.global [%0], [%1], 16;" :: "r"(s), "l"(g));
    }
    asm volatile("cp.async.commit_group;");
}
__device__ __forceinline__ void loadA(const __nv_bfloat16* __restrict__ znb,
                                      int rowBase, uint32_t sA, int tid) {
#pragma unroll 8
    for (int idx = tid; idx < TM * 64; idx += 256) {
        int r = idx >> 6;
        int c = idx & 63;
        const void* g = znb + (size_t)(rowBase + r) * D + c * 8;
        uint32_t s = sA + r * 1024 + ((c ^ (r & 7)) << 4);
        asm volatile("cp.async.cg.shared.global [%0], [%1], 16;" :: "r"(s), "l"(g));
    }
    asm volatile("cp.async.commit_group;");
}

// emit accumulated row partials for band r into slot (r*33 + offFirst)
__device__ __forceinline__ void emit_rows(float rowp[2][2], int r, int offFirst,
                                          float* scratch, int tid, int lane,
                                          int warpM, int warpN) {
    __syncthreads();   // protect scratch from lagging readers
#pragma unroll
    for (int mt = 0; mt < 2; mt++)
#pragma unroll
        for (int h = 0; h < 2; h++) {
            float p = rowp[mt][h];
            p += __shfl_xor_sync(0xffffffffu, p, 1);
            p += __shfl_xor_sync(0xffffffffu, p, 2);
            rowp[mt][h] = p;
        }
    if ((lane & 3) == 0) {
#pragma unroll
        for (int mt = 0; mt < 2; mt++)
#pragma unroll
            for (int h = 0; h < 2; h++) {
                int rl = warpM * 32 + mt * 16 + (lane >> 2) + 8 * h;
                scratch[rl * 2 + warpN] = rowp[mt][h];
            }
    }
    __syncthreads();
    if (tid < TM)
        g_rs[(r * 33 + offFirst) * 128 + tid] = scratch[tid * 2] + scratch[tid * 2 + 1];
}

__global__ void __launch_bounds__(256, 1) denom_kernel() {
    extern __shared__ char smem[];
    const int tid = threadIdx.x;
    const int lane = tid & 31;
    const int wid = tid >> 5;
    const int warpM = wid & 3;
    const int warpN = wid >> 2;
    const int cta = blockIdx.x;

    const __nv_bfloat16* __restrict__ znb = g_znb;
    uint32_t sA = smem_u32(smem) + SA_OFF;
    uint32_t sB = smem_u32(smem) + SB_OFF;
    float* scratch = (float*)(smem + SRED_OFF);

    const int aRow = warpM * 32 + (lane & 15);
    const uint32_t aBase = sA + aRow * 1024;
    const int aXor = aRow & 7;
    const int aC = lane >> 4;
    const int bRow = warpN * 64 + (lane & 7) + ((lane >> 4) << 3);
    const int bXor = bRow & 7;
    const int bC = (lane >> 3) & 1;

    const int istart = (cta * NTILES) / NCTA;
    const int iend = ((cta + 1) * NTILES) / NCTA;
    const int nIts = (iend - istart) * 4;

    int rcur, offcur, ccur;
    tmap(istart, rcur, offcur, ccur);
    int rprev = rcur;
    int offFirst = offcur;

    loadA(znb, rcur * TM, sA, tid);
    asm volatile("cp.async.wait_group 0;");
    __syncthreads();
    prefetchB(znb, ccur * TM, 0, sB, tid);
    prefetchB(znb, ccur * TM, 1, sB + SB_BYTES, tid);

    float acc[2][8][4];
#pragma unroll
    for (int mt = 0; mt < 2; mt++)
#pragma unroll
        for (int nt = 0; nt < 8; nt++)
#pragma unroll
            for (int j = 0; j < 4; j++) acc[mt][nt][j] = 0.f;
    float rowp[2][2] = {{0.f, 0.f}, {0.f, 0.f}};

    for (int git = 0; git < nIts; ++git) {
        const int kc = git & 3;
        if (kc == 0 && git > 0) {
            tmap(istart + (git >> 2), rcur, offcur, ccur);
            if (rcur != rprev) {
                emit_rows(rowp, rprev, offFirst, scratch, tid, lane, warpM, warpN);
                rowp[0][0] = rowp[0][1] = rowp[1][0] = rowp[1][1] = 0.f;
                offFirst = offcur;
                asm volatile("cp.async.wait_group 0;");
                __syncthreads();
                loadA(znb, rcur * TM, sA, tid);
                asm volatile("cp.async.wait_group 0;");
                __syncthreads();
                rprev = rcur;
            }
        }
        asm volatile("cp.async.wait_group 1;");
        __syncthreads();

        if (git + 2 < nIts) {
            int r2, o2, c2;
            tmap(istart + ((git + 2) >> 2), r2, o2, c2);
            prefetchB(znb, c2 * TM, (git + 2) & 3, sB + ((git + 2) % 3) * SB_BYTES, tid);
        } else {
            asm volatile("cp.async.commit_group;");
        }

        const uint32_t bufB = sB + (git % 3) * SB_BYTES;
#pragma unroll
        for (int s = 0; s < 8; ++s) {
            uint32_t af[2][4];
#pragma unroll
            for (int mt = 0; mt < 2; mt++)
                ldsm4(af[mt], aBase + mt * 16384 + (((kc * 16 + s * 2 + aC) ^ aXor) << 4));
#pragma unroll
            for (int bg = 0; bg < 4; bg++) {
                uint32_t bf[4];
                ldsm4(bf, bufB + (bRow + bg * 16) * 256 + (((s * 2 + bC) ^ bXor) << 4));
#pragma unroll
                for (int mt = 0; mt < 2; mt++) {
                    mma_bf16(acc[mt][bg * 2], af[mt], bf);
                    mma_bf16(acc[mt][bg * 2 + 1], af[mt], bf + 2);
                }
            }
        }

        if (kc == 3) {
            if (offcur == 0) {
                // diagonal tile: masked row sums only, no syncs
                const int colWBase = ccur * TM + warpN * 64 + (lane & 3) * 2;
                const int r0g = rcur * TM + warpM * 32 + (lane >> 2);
#pragma unroll
                for (int mt = 0; mt < 2; mt++) {
                    int r0 = r0g + mt * 16, r1 = r0 + 8;
#pragma unroll
                    for (int nt = 0; nt < 8; nt++) {
                        int c0 = colWBase + nt * 8;
                        float e0 = ex2f(acc[mt][nt][0]);
                        float e1 = ex2f(acc[mt][nt][1]);
                        float e2 = ex2f(acc[mt][nt][2]);
                        float e3 = ex2f(acc[mt][nt][3]);
                        rowp[mt][0] += (c0 != r0 ? e0 : 0.f) + (c0 + 1 != r0 ? e1 : 0.f);
                        rowp[mt][1] += (c0 != r1 ? e2 : 0.f) + (c0 + 1 != r1 ? e3 : 0.f);
                        acc[mt][nt][0] = 0.f; acc[mt][nt][1] = 0.f;
                        acc[mt][nt][2] = 0.f; acc[mt][nt][3] = 0.f;
                    }
                }
            } else {
                float colp[8][2];
#pragma unroll
                for (int nt = 0; nt < 8; nt++) { colp[nt][0] = 0.f; colp[nt][1] = 0.f; }
#pragma unroll
                for (int mt = 0; mt < 2; mt++) {
#pragma unroll
                    for (int nt = 0; nt < 8; nt++) {
                        float e0 = ex2f(acc[mt][nt][0]);
                        float e1 = ex2f(acc[mt][nt][1]);
                        float e2 = ex2f(acc[mt][nt][2]);
                        float e3 = ex2f(acc[mt][nt][3]);
                        rowp[mt][0] += e0 + e1;
                        rowp[mt][1] += e2 + e3;
                        colp[nt][0] += e0 + e2;
                        colp[nt][1] += e1 + e3;
                        acc[mt][nt][0] = 0.f; acc[mt][nt][1] = 0.f;
                        acc[mt][nt][2] = 0.f; acc[mt][nt][3] = 0.f;
                    }
                }
                // col reduce across rows (xor 4,8,16), single sync
#pragma unroll
                for (int nt = 0; nt < 8; nt++)
#pragma unroll
                    for (int q = 0; q < 2; q++) {
                        float p = colp[nt][q];
                        p += __shfl_xor_sync(0xffffffffu, p, 4);
                        p += __shfl_xor_sync(0xffffffffu, p, 8);
                        p += __shfl_xor_sync(0xffffffffu, p, 16);
                        colp[nt][q] = p;
                    }
                if (lane < 4) {
#pragma unroll
                    for (int nt = 0; nt < 8; nt++)
#pragma unroll
                        for (int q = 0; q < 2; q++) {
                            int col = nt * 8 + lane * 2 + q;
                            scratch[(warpN * 4 + warpM) * 64 + col] = colp[nt][q];
                        }
                }
                __syncthreads();
                if (tid < TM) {
                    int wn = tid >> 6, cl = tid & 63;
                    float s = scratch[(wn * 4 + 0) * 64 + cl] + scratch[(wn * 4 + 1) * 64 + cl]
                            + scratch[(wn * 4 + 2) * 64 + cl] + scratch[(wn * 4 + 3) * 64 + cl];
                    g_cs[(rcur * 33 + offcur) * 128 + tid] = s;
                }
            }
        }
    }
    emit_rows(rowp, rprev, offFirst, scratch, tid, lane, warpM, warpN);
}

// ---------------------------------------------------------------------------
// 3) fused loss + mean (deterministic last-block final reduce)
// ---------------------------------------------------------------------------
__global__ void loss_mean_kernel(const float* __restrict__ zi,
                                 const float* __restrict__ zj,
                                 float* __restrict__ out, int B) {
    __shared__ float wsum[8];
    __shared__ unsigned int sflag;
    int lane = threadIdx.x & 31;
    int wrp = threadIdx.x >> 5;
    int rowg = blockIdx.x * 8 + wrp;     // global row (0..8191)
    int N = 2 * B;

    // denominator gather
    int b = rowg >> 7, lr = rowg & 127;
    float d = g_rs[(b * 33 + lane) * 128 + lr];
    if (lane == 0 && b < 32) d += g_rs[(b * 33 + 32) * 128 + lr];
    {
        int off2 = lane + 1;
        int rr = (b - off2 + 64) & 63;
        if (off2 < 32 || rr < 32) d += g_cs[(rr * 33 + off2) * 128 + lr];
    }
#pragma unroll
    for (int o = 16; o > 0; o >>= 1) d += __shfl_xor_sync(0xffffffffu, d, o);

    // positives from raw fp32 inputs
    int row = (rowg < B) ? rowg : (rowg - B);
    const float* a = zi + (size_t)row * D;
    const float* bb = zj + (size_t)row * D;
    float dot = 0.f;
#pragma unroll
    for (int q = 0; q < D / (32 * 4); q++) {
        float4 va = *(const float4*)(a + (q * 32 + lane) * 4);
        float4 vb = *(const float4*)(bb + (q * 32 + lane) * 4);
        dot += va.x * vb.x + va.y * vb.y + va.z * vb.z + va.w * vb.w;
    }
#pragma unroll
    for (int o = 16; o > 0; o >>= 1) dot += __shfl_xor_sync(0xffffffffu, dot, o);

    if (lane == 0) {
        int prow = (rowg < B) ? (rowg + B) : (rowg - B);
        float sim = dot * g_rinv[rowg] * g_rinv[prow] * TEMP_INV;
        wsum[wrp] = logf(d + 1e-8f) - sim;
    }
    __syncthreads();
    if (threadIdx.x == 0) {
        float s = 0.f;
#pragma unroll
        for (int i = 0; i < 8; i++) s += wsum[i];
        g_bpart[blockIdx.x] = s;
        __threadfence();
        sflag = atomicInc(&g_ctr, NLBLK - 1);
    }
    __syncthreads();
    if (sflag == NLBLK - 1) {
        // last block: deterministic fixed-order final sum
        __shared__ float red[256];
        int t = threadIdx.x;
        const volatile float* bp = g_bpart;
        float s = 0.f;
#pragma unroll
        for (int i = 0; i < NLBLK / 256; i++) s += bp[t + i * 256];
        red[t] = s;
        __syncthreads();
#pragma unroll
        for (int st = 128; st > 0; st >>= 1) {
            if (t < st) red[t] += red[t + st];
            __syncthreads();
        }
        if (t == 0) out[0] = red[0] / (float)N;
    }
}

// ---------------------------------------------------------------------------
extern "C" void kernel_launch(void* const* d_in, const int* in_sizes, int n_in,
                              void* d_out, int out_size) {
    const float* zi = (const float*)d_in[0];
    const float* zj = (const float*)d_in[1];
    int B = in_sizes[0] / D;  // 4096
    int N = 2 * B;            // 8192

    cudaFuncSetAttribute(denom_kernel, cudaFuncAttributeMaxDynamicSharedMemorySize, SMEM_TOTAL);

    normalize_kernel<<<N, 128>>>(zi, zj, B);
    denom_kernel<<<NCTA, 256, SMEM_TOTAL>>>();
    loss_mean_kernel<<<NLBLK, 256>>>(zi, zj, (float*)d_out, B);
}

// round 8
// speedup vs baseline: 1.9412x; 1.0382x over previous
#include <cuda_runtime.h>
#include <cuda_bf16.h>
#include <math.h>
#include <stdint.h>

// NT-Xent loss. B=4096, D=512. Symmetric fused bf16 HMMA sim-GEMM.
// Inputs pre-scaled by sqrt(2*log2(e)) so epilogue is a bare ex2.
// normalize computes positives (fp32) in the same pass.

#define D 512
#define MAXN 8192
#define TEMP_INV 2.0f
#define QSCALE 1.6986436f   // sqrt(2 * log2(e)); acc = 2*log2(e)*sim
#define NCTA 148
#define NB 64
#define NTILES 2080

#define TM 128
#define KCHUNK 128

#define SA_OFF 0
#define SA_BYTES (TM * D * 2)
#define SB_OFF SA_BYTES
#define SB_BYTES (TM * KCHUNK * 2)
#define NSTAGE 3
#define SRED_OFF (SB_OFF + NSTAGE * SB_BYTES)
#define SMEM_TOTAL (SRED_OFF + 2048)

#define NLBLK 1024

__device__ __nv_bfloat16 g_znb[(size_t)MAXN * D];
__device__ float g_pos[MAXN / 2];
__device__ float g_rs[NB * 33 * 128];
__device__ float g_cs[NB * 33 * 128];
__device__ float g_bpart[NLBLK];
__device__ unsigned int g_ctr = 0;

__device__ __forceinline__ uint32_t smem_u32(const void* p) {
    uint32_t a;
    asm("{ .reg .u64 t; cvta.to.shared.u64 t, %1; cvt.u32.u64 %0, t; }" : "=r"(a) : "l"(p));
    return a;
}
__device__ __forceinline__ float ex2f(float x) {
    float r;
    asm("ex2.approx.f32 %0, %1;" : "=f"(r) : "f"(x));
    return r;
}
__device__ __forceinline__ void ldsm4(uint32_t* r, uint32_t addr) {
    asm volatile("ldmatrix.sync.aligned.m8n8.x4.shared.b16 {%0,%1,%2,%3}, [%4];"
                 : "=r"(r[0]), "=r"(r[1]), "=r"(r[2]), "=r"(r[3]) : "r"(addr));
}
__device__ __forceinline__ void mma_bf16(float* c, const uint32_t* a, const uint32_t* b) {
    asm volatile(
        "mma.sync.aligned.m16n8k16.row.col.f32.bf16.bf16.f32 "
        "{%0,%1,%2,%3}, {%4,%5,%6,%7}, {%8,%9}, {%0,%1,%2,%3};"
        : "+f"(c[0]), "+f"(c[1]), "+f"(c[2]), "+f"(c[3])
        : "r"(a[0]), "r"(a[1]), "r"(a[2]), "r"(a[3]), "r"(b[0]), "r"(b[1]));
}
__device__ __forceinline__ void tmap(int t, int& r, int& off, int& c) {
    if (t < 32 * 33) { r = t / 33; off = t - r * 33; }
    else { int u = t - 32 * 33; r = 32 + u / 32; off = u - (u / 32) * 32; }
    c = (r + off) & 63;
}

// ---------------------------------------------------------------------------
// 1) normalize pair (zi[row], zj[row]) -> bf16(zn*QSCALE) rows (row, row+B),
//    fp32 positive sim -> g_pos[row]; zero g_rs.
// ---------------------------------------------------------------------------
__global__ void normalize_kernel(const float* __restrict__ zi,
                                 const float* __restrict__ zj, int B) {
    int row = blockIdx.x;
    int t = threadIdx.x;
    int lane = t & 31, w = t >> 5;
    float4 vi = *(const float4*)(zi + (size_t)row * D + t * 4);
    float4 vj = *(const float4*)(zj + (size_t)row * D + t * 4);
    float ssi = vi.x * vi.x + vi.y * vi.y + vi.z * vi.z + vi.w * vi.w;
    float ssj = vj.x * vj.x + vj.y * vj.y + vj.z * vj.z + vj.w * vj.w;
    float dij = vi.x * vj.x + vi.y * vj.y + vi.z * vj.z + vi.w * vj.w;
#pragma unroll
    for (int o = 16; o > 0; o >>= 1) {
        ssi += __shfl_xor_sync(0xffffffffu, ssi, o);
        ssj += __shfl_xor_sync(0xffffffffu, ssj, o);
        dij += __shfl_xor_sync(0xffffffffu, dij, o);
    }
    __shared__ float s3[4][3];
    if (lane == 0) { s3[w][0] = ssi; s3[w][1] = ssj; s3[w][2] = dij; }
    __syncthreads();
    ssi = s3[0][0] + s3[1][0] + s3[2][0] + s3[3][0];
    ssj = s3[0][1] + s3[1][1] + s3[2][1] + s3[3][1];
    dij = s3[0][2] + s3[1][2] + s3[2][2] + s3[3][2];
    float ri = rsqrtf(ssi), rj = rsqrtf(ssj);
    float sci = ri * QSCALE, scj = rj * QSCALE;
    __nv_bfloat16* oi = g_znb + (size_t)row * D + t * 4;
    oi[0] = __float2bfloat16(vi.x * sci);
    oi[1] = __float2bfloat16(vi.y * sci);
    oi[2] = __float2bfloat16(vi.z * sci);
    oi[3] = __float2bfloat16(vi.w * sci);
    __nv_bfloat16* oj = g_znb + (size_t)(row + B) * D + t * 4;
    oj[0] = __float2bfloat16(vj.x * scj);
    oj[1] = __float2bfloat16(vj.y * scj);
    oj[2] = __float2bfloat16(vj.z * scj);
    oj[3] = __float2bfloat16(vj.w * scj);
    if (t == 0) g_pos[row] = dij * ri * rj * TEMP_INV;
    int zidx = row * 128 + t;
    if (zidx < NB * 33 * 128) g_rs[zidx] = 0.0f;
}

// ---------------------------------------------------------------------------
// 2) symmetric fused HMMA GEMM, segment-accumulated row sums
// ---------------------------------------------------------------------------
__device__ __forceinline__ void prefetchB(const __nv_bfloat16* __restrict__ znb,
                                          int colBase, int kc, uint32_t smemBuf, int tid) {
#pragma unroll
    for (int i = 0; i < 8; i++) {
        int idx = tid + i * 256;
        int n = idx >> 4;
        int c = idx & 15;
        const void* g = znb + (size_t)(colBase + n) * D + kc * KCHUNK + c * 8;
        uint32_t s = smemBuf + n * 256 + ((c ^ (n & 7)) << 4);
        asm volatile("cp.async.cg.shared.global [%0], [%1], 16;" :: "r"(s), "l"(g));
    }
    asm volatile("cp.async.commit_group;");
}
__device__ __forceinline__ void loadA(const __nv_bfloat16* __restrict__ znb,
                                      int rowBase, uint32_t sA, int tid) {
#pragma unroll 8
    for (int idx = tid; idx < TM * 64; idx += 256) {
        int r = idx >> 6;
        int c = idx & 63;
        const void* g = znb + (size_t)(rowBase + r) * D + c * 8;
        uint32_t s = sA + r * 1024 + ((c ^ (r & 7)) << 4);
        asm volatile("cp.async.cg.shared.global [%0], [%1], 16;" :: "r"(s), "l"(g));
    }
    asm volatile("cp.async.commit_group;");
}

__device__ __forceinline__ void emit_rows(float rowp[2][2], int r, int offFirst,
                                          float* scratch, int tid, int lane,
                                          int warpM, int warpN) {
    __syncthreads();
#pragma unroll
    for (int mt = 0; mt < 2; mt++)
#pragma unroll
        for (int h = 0; h < 2; h++) {
            float p = rowp[mt][h];
            p += __shfl_xor_sync(0xffffffffu, p, 1);
            p += __shfl_xor_sync(0xffffffffu, p, 2);
            rowp[mt][h] = p;
        }
    if ((lane & 3) == 0) {
#pragma unroll
        for (int mt = 0; mt < 2; mt++)
#pragma unroll
            for (int h = 0; h < 2; h++) {
                int rl = warpM * 32 + mt * 16 + (lane >> 2) + 8 * h;
                scratch[rl * 2 + warpN] = rowp[mt][h];
            }
    }
    __syncthreads();
    if (tid < TM)
        g_rs[(r * 33 + offFirst) * 128 + tid] = scratch[tid * 2] + scratch[tid * 2 + 1];
}

__global__ void __launch_bounds__(256, 1) denom_kernel() {
    extern __shared__ char smem[];
    const int tid = threadIdx.x;
    const int lane = tid & 31;
    const int wid = tid >> 5;
    const int warpM = wid & 3;
    const int warpN = wid >> 2;
    const int cta = blockIdx.x;

    const __nv_bfloat16* __restrict__ znb = g_znb;
    uint32_t sA = smem_u32(smem) + SA_OFF;
    uint32_t sB = smem_u32(smem) + SB_OFF;
    float* scratch = (float*)(smem + SRED_OFF);

    const int aRow = warpM * 32 + (lane & 15);
    const uint32_t aBase = sA + aRow * 1024;
    const int aXor = aRow & 7;
    const int aC = lane >> 4;
    const int bRow = warpN * 64 + (lane & 7) + ((lane >> 4) << 3);
    const int bXor = bRow & 7;
    const int bC = (lane >> 3) & 1;

    const int istart = (cta * NTILES) / NCTA;
    const int iend = ((cta + 1) * NTILES) / NCTA;
    const int nIts = (iend - istart) * 4;

    int rcur, offcur, ccur;
    tmap(istart, rcur, offcur, ccur);
    int rprev = rcur;
    int offFirst = offcur;

    loadA(znb, rcur * TM, sA, tid);
    asm volatile("cp.async.wait_group 0;");
    __syncthreads();
    prefetchB(znb, ccur * TM, 0, sB, tid);
    prefetchB(znb, ccur * TM, 1, sB + SB_BYTES, tid);

    float acc[2][8][4];
#pragma unroll
    for (int mt = 0; mt < 2; mt++)
#pragma unroll
        for (int nt = 0; nt < 8; nt++)
#pragma unroll
            for (int j = 0; j < 4; j++) acc[mt][nt][j] = 0.f;
    float rowp[2][2] = {{0.f, 0.f}, {0.f, 0.f}};

    for (int git = 0; git < nIts; ++git) {
        const int kc = git & 3;
        if (kc == 0 && git > 0) {
            tmap(istart + (git >> 2), rcur, offcur, ccur);
            if (rcur != rprev) {
                emit_rows(rowp, rprev, offFirst, scratch, tid, lane, warpM, warpN);
                rowp[0][0] = rowp[0][1] = rowp[1][0] = rowp[1][1] = 0.f;
                offFirst = offcur;
                asm volatile("cp.async.wait_group 0;");
                __syncthreads();
                loadA(znb, rcur * TM, sA, tid);
                asm volatile("cp.async.wait_group 0;");
                __syncthreads();
                rprev = rcur;
            }
        }
        asm volatile("cp.async.wait_group 1;");
        __syncthreads();

        if (git + 2 < nIts) {
            int r2, o2, c2;
            tmap(istart + ((git + 2) >> 2), r2, o2, c2);
            prefetchB(znb, c2 * TM, (git + 2) & 3, sB + ((git + 2) % 3) * SB_BYTES, tid);
        } else {
            asm volatile("cp.async.commit_group;");
        }

        const uint32_t bufB = sB + (git % 3) * SB_BYTES;
#pragma unroll
        for (int s = 0; s < 8; ++s) {
            uint32_t af[2][4];
#pragma unroll
            for (int mt = 0; mt < 2; mt++)
                ldsm4(af[mt], aBase + mt * 16384 + (((kc * 16 + s * 2 + aC) ^ aXor) << 4));
#pragma unroll
            for (int bg = 0; bg < 4; bg++) {
                uint32_t bf[4];
                ldsm4(bf, bufB + (bRow + bg * 16) * 256 + (((s * 2 + bC) ^ bXor) << 4));
#pragma unroll
                for (int mt = 0; mt < 2; mt++) {
                    mma_bf16(acc[mt][bg * 2], af[mt], bf);
                    mma_bf16(acc[mt][bg * 2 + 1], af[mt], bf + 2);
                }
            }
        }

        if (kc == 3) {
            if (offcur == 0) {
                const int colWBase = ccur * TM + warpN * 64 + (lane & 3) * 2;
                const int r0g = rcur * TM + warpM * 32 + (lane >> 2);
#pragma unroll
                for (int mt = 0; mt < 2; mt++) {
                    int r0 = r0g + mt * 16, r1 = r0 + 8;
#pragma unroll
                    for (int nt = 0; nt < 8; nt++) {
                        int c0 = colWBase + nt * 8;
                        float e0 = ex2f(acc[mt][nt][0]);
                        float e1 = ex2f(acc[mt][nt][1]);
                        float e2 = ex2f(acc[mt][nt][2]);
                        float e3 = ex2f(acc[mt][nt][3]);
                        rowp[mt][0] += (c0 != r0 ? e0 : 0.f) + (c0 + 1 != r0 ? e1 : 0.f);
                        rowp[mt][1] += (c0 != r1 ? e2 : 0.f) + (c0 + 1 != r1 ? e3 : 0.f);
                        acc[mt][nt][0] = 0.f; acc[mt][nt][1] = 0.f;
                        acc[mt][nt][2] = 0.f; acc[mt][nt][3] = 0.f;
                    }
                }
            } else {
                float colp[8][2];
#pragma unroll
                for (int nt = 0; nt < 8; nt++) { colp[nt][0] = 0.f; colp[nt][1] = 0.f; }
#pragma unroll
                for (int mt = 0; mt < 2; mt++) {
#pragma unroll
                    for (int nt = 0; nt < 8; nt++) {
                        float e0 = ex2f(acc[mt][nt][0]);
                        float e1 = ex2f(acc[mt][nt][1]);
                        float e2 = ex2f(acc[mt][nt][2]);
                        float e3 = ex2f(acc[mt][nt][3]);
                        rowp[mt][0] += e0 + e1;
                        rowp[mt][1] += e2 + e3;
                        colp[nt][0] += e0 + e2;
                        colp[nt][1] += e1 + e3;
                        acc[mt][nt][0] = 0.f; acc[mt][nt][1] = 0.f;
                        acc[mt][nt][2] = 0.f; acc[mt][nt][3] = 0.f;
                    }
                }
#pragma unroll
                for (int nt = 0; nt < 8; nt++)
#pragma unroll
                    for (int q = 0; q < 2; q++) {
                        float p = colp[nt][q];
                        p += __shfl_xor_sync(0xffffffffu, p, 4);
                        p += __shfl_xor_sync(0xffffffffu, p, 8);
                        p += __shfl_xor_sync(0xffffffffu, p, 16);
                        colp[nt][q] = p;
                    }
                if (lane < 4) {
#pragma unroll
                    for (int nt = 0; nt < 8; nt++)
#pragma unroll
                        for (int q = 0; q < 2; q++) {
                            int col = nt * 8 + lane * 2 + q;
                            scratch[(warpN * 4 + warpM) * 64 + col] = colp[nt][q];
                        }
                }
                __syncthreads();
                if (tid < TM) {
                    int wn = tid >> 6, cl = tid & 63;
                    float s = scratch[(wn * 4 + 0) * 64 + cl] + scratch[(wn * 4 + 1) * 64 + cl]
                            + scratch[(wn * 4 + 2) * 64 + cl] + scratch[(wn * 4 + 3) * 64 + cl];
                    g_cs[(rcur * 33 + offcur) * 128 + tid] = s;
                }
            }
        }
    }
    emit_rows(rowp, rprev, offFirst, scratch, tid, lane, warpM, warpN);
}

// ---------------------------------------------------------------------------
// 3) loss + mean: gather denominator slots, use precomputed positives
// ---------------------------------------------------------------------------
__global__ void loss_mean_kernel(float* __restrict__ out, int B) {
    __shared__ float wsum[8];
    __shared__ unsigned int sflag;
    int lane = threadIdx.x & 31;
    int wrp = threadIdx.x >> 5;
    int rowg = blockIdx.x * 8 + wrp;
    int N = 2 * B;

    int b = rowg >> 7, lr = rowg & 127;
    float d = g_rs[(b * 33 + lane) * 128 + lr];
    if (lane == 0 && b < 32) d += g_rs[(b * 33 + 32) * 128 + lr];
    {
        int off2 = lane + 1;
        int rr = (b - off2 + 64) & 63;
        if (off2 < 32 || rr < 32) d += g_cs[(rr * 33 + off2) * 128 + lr];
    }
#pragma unroll
    for (int o = 16; o > 0; o >>= 1) d += __shfl_xor_sync(0xffffffffu, d, o);

    if (lane == 0) {
        float pos = g_pos[(rowg < B) ? rowg : (rowg - B)];
        wsum[wrp] = logf(d + 1e-8f) - pos;
    }
    __syncthreads();
    if (threadIdx.x == 0) {
        float s = 0.f;
#pragma unroll
        for (int i = 0; i < 8; i++) s += wsum[i];
        g_bpart[blockIdx.x] = s;
        __threadfence();
        sflag = atomicInc(&g_ctr, NLBLK - 1);
    }
    __syncthreads();
    if (sflag == NLBLK - 1) {
        __shared__ float red[256];
        int t = threadIdx.x;
        const volatile float* bp = g_bpart;
        float s = 0.f;
#pragma unroll
        for (int i = 0; i < NLBLK / 256; i++) s += bp[t + i * 256];
        red[t] = s;
        __syncthreads();
#pragma unroll
        for (int st = 128; st > 0; st >>= 1) {
            if (t < st) red[t] += red[t + st];
            __syncthreads();
        }
        if (t == 0) out[0] = red[0] / (float)N;
    }
}

// ---------------------------------------------------------------------------
extern "C" void kernel_launch(void* const* d_in, const int* in_sizes, int n_in,
                              void* d_out, int out_size) {
    const float* zi = (const float*)d_in[0];
    const float* zj = (const float*)d_in[1];
    int B = in_sizes[0] / D;  // 4096

    cudaFuncSetAttribute(denom_kernel, cudaFuncAttributeMaxDynamicSharedMemorySize, SMEM_TOTAL);

    normalize_kernel<<<B, 128>>>(zi, zj, B);
    denom_kernel<<<NCTA, 256, SMEM_TOTAL>>>();
    loss_mean_kernel<<<NLBLK, 256>>>((float*)d_out, B);
}